// round 13
// baseline (speedup 1.0000x reference)
#include <cuda_runtime.h>
#include <cuda_bf16.h>
#include <math.h>
#include <stdint.h>

// ---------------- problem constants ----------------
#define NB      1024
#define SS      128
#define DD      128
#define HH      4
#define CC      32
#define LL      2
#define M_ROWS  (NB * SS)
#define MSZ     (M_ROWS * DD)
#define EPS     1e-5f
#define INV_M   (1.0f / (float)M_ROWS)
#define NSLOT   11

// ---------------- scratch ----------------
__device__ float g_h[MSZ];
__device__ float g_t[MSZ];
__device__ float g_q[MSZ];
__device__ float g_k[MSZ];
__device__ float g_v[MSZ];
__device__ float g_s[MSZ];
__device__ float g_a[MSZ];
__device__ float g_o[MSZ];
__device__ float g_f[MSZ];
__device__ float g_stat_sum[NSLOT][DD];
__device__ float g_stat_sq[NSLOT][DD];

// ================= helpers =================
__device__ __forceinline__ uint32_t smem_u32(const void* p) {
    uint32_t a;
    asm("{ .reg .u64 t; cvta.to.shared.u64 t, %1; cvt.u32.u64 %0, t; }" : "=r"(a) : "l"(p));
    return a;
}
__device__ __forceinline__ uint32_t packbf(float a, float b) {
    __nv_bfloat162 t = __floats2bfloat162_rn(a, b);
    return *(uint32_t*)&t;
}
__device__ __forceinline__ void bn_affine(const float* sum, const float* sq,
                                          const float* g, const float* b, int c,
                                          float& sc, float& sh) {
    float m = sum[c] * INV_M;
    float var = sq[c] * INV_M - m * m;
    float s = g[c] * rsqrtf(var + EPS);
    sc = s;
    sh = b[c] - m * s;
}

#define LDSM_X4(r0, r1, r2, r3, addr) \
    asm volatile("ldmatrix.sync.aligned.m8n8.x4.shared.b16 {%0,%1,%2,%3}, [%4];" \
                 : "=r"(r0), "=r"(r1), "=r"(r2), "=r"(r3) : "r"(addr))

__device__ __forceinline__ void mma_bf16(float c[4],
                                         uint32_t a0, uint32_t a1, uint32_t a2, uint32_t a3,
                                         uint32_t b0, uint32_t b1) {
    asm volatile(
        "mma.sync.aligned.m16n8k16.row.col.f32.bf16.bf16.f32 "
        "{%0,%1,%2,%3}, {%4,%5,%6,%7}, {%8,%9}, {%0,%1,%2,%3};"
        : "+f"(c[0]), "+f"(c[1]), "+f"(c[2]), "+f"(c[3])
        : "r"(a0), "r"(a1), "r"(a2), "r"(a3), "r"(b0), "r"(b1));
}

// ---------------- zero all stat slots (start of graph) ----------------
__global__ void zero_stats_kernel() {
    int i = blockIdx.x * blockDim.x + threadIdx.x;
    if (i < NSLOT * DD) {
        ((float*)g_stat_sum)[i] = 0.0f;
        ((float*)g_stat_sq)[i] = 0.0f;
    }
}

// ---------------- no-op spacer: shifts profiler capture slot onto the QKVS GEMM ----------------
__global__ void noop_kernel() {}

// ================= GEMM: up to 4 weight sets share one converted A tile =================
#define BSTR 136
#define A_TILE_E (256 * BSTR)
#define W_TILE_E (128 * BSTR)
#define GEMM_SMEM ((2 * A_TILE_E + 2 * W_TILE_E) * 2 + 1024)

__global__ void __launch_bounds__(512)
gemm_tc_kernel(const float* __restrict__ A,
               const float* __restrict__ sumA, const float* __restrict__ sqA,
               const float* __restrict__ gA, const float* __restrict__ bA,
               const float* W0, const float* W1, const float* W2, const float* W3,
               const float* b0, const float* b1, const float* b2, const float* b3,
               float* C0, float* C1, float* C2, float* C3,
               float* sum0, float* sum1, float* sum2, float* sum3,
               float* sq0, float* sq1, float* sq2, float* sq3,
               int nW) {
    extern __shared__ __nv_bfloat16 smem[];
    __nv_bfloat16* AH = smem;
    __nv_bfloat16* AL = smem + A_TILE_E;
    __nv_bfloat16* WH = smem + 2 * A_TILE_E;
    __nv_bfloat16* WL = smem + 2 * A_TILE_E + W_TILE_E;
    float* sAff = (float*)(smem + 2 * A_TILE_E + 2 * W_TILE_E);   // [256]

    const float* Wj[4] = {W0, W1, W2, W3};
    const float* bj[4] = {b0, b1, b2, b3};
    float* Cj[4] = {C0, C1, C2, C3};
    float* sumj[4] = {sum0, sum1, sum2, sum3};
    float* sqj[4] = {sq0, sq1, sq2, sq3};

    const int tid = threadIdx.x;
    const long rowBase = (long)blockIdx.x * 256;

    if (gA && tid < 128) {
        float sc, sh;
        bn_affine(sumA, sqA, gA, bA, tid, sc, sh);
        sAff[tid] = sc;
        sAff[128 + tid] = sh;
    }
    __syncthreads();

    for (int idx = tid; idx < 8192; idx += 512) {
        int r = idx >> 5, k0 = (idx & 31) * 4;
        float4 v = *(const float4*)(A + (rowBase + r) * 128 + k0);
        if (gA) {
            float4 s = *(const float4*)(sAff + k0);
            float4 t = *(const float4*)(sAff + 128 + k0);
            v.x = v.x * s.x + t.x; v.y = v.y * s.y + t.y;
            v.z = v.z * s.z + t.z; v.w = v.w * s.w + t.w;
        }
        float h0 = __bfloat162float(__float2bfloat16_rn(v.x));
        float h1 = __bfloat162float(__float2bfloat16_rn(v.y));
        float h2 = __bfloat162float(__float2bfloat16_rn(v.z));
        float h3 = __bfloat162float(__float2bfloat16_rn(v.w));
        *(uint2*)(AH + r * BSTR + k0) = make_uint2(packbf(v.x, v.y), packbf(v.z, v.w));
        *(uint2*)(AL + r * BSTR + k0) =
            make_uint2(packbf(v.x - h0, v.y - h1), packbf(v.z - h2, v.w - h3));
    }

    const int warp = tid >> 5, lane = tid & 31;
    const int wm = warp >> 2, wn = warp & 3;
    const int m0 = wm * 64, n0 = wn * 32;
    const int lrow = lane & 15, lhalf = (lane >> 4) * 8;
    const int cr = lane >> 2, cc2 = (lane & 3) * 2;

    const uint32_t uAH = smem_u32(AH), uAL = smem_u32(AL);
    const uint32_t uWH = smem_u32(WH), uWL = smem_u32(WL);

    for (int j = 0; j < nW; j++) {
        if (j > 0) __syncthreads();
        const float* W = Wj[j];
        for (int idx = tid; idx < 4096; idx += 512) {
            int r = idx >> 5, k0 = (idx & 31) * 4;
            float4 v = *(const float4*)(W + r * 128 + k0);
            float h0 = __bfloat162float(__float2bfloat16_rn(v.x));
            float h1 = __bfloat162float(__float2bfloat16_rn(v.y));
            float h2 = __bfloat162float(__float2bfloat16_rn(v.z));
            float h3 = __bfloat162float(__float2bfloat16_rn(v.w));
            *(uint2*)(WH + r * BSTR + k0) = make_uint2(packbf(v.x, v.y), packbf(v.z, v.w));
            *(uint2*)(WL + r * BSTR + k0) =
                make_uint2(packbf(v.x - h0, v.y - h1), packbf(v.z - h2, v.w - h3));
        }
        __syncthreads();

        float acc[4][4][4];
#pragma unroll
        for (int mt = 0; mt < 4; mt++)
#pragma unroll
            for (int nt = 0; nt < 4; nt++)
#pragma unroll
                for (int i = 0; i < 4; i++) acc[mt][nt][i] = 0.0f;

#pragma unroll
        for (int ks = 0; ks < 8; ks++) {
            const uint32_t colOff = (uint32_t)(ks * 16 + lhalf) * 2;
            uint32_t bhi[4][2];
#pragma unroll
            for (int g = 0; g < 2; g++) {
                uint32_t r0, r1, r2, r3;
                uint32_t addr = uWH + ((uint32_t)(n0 + g * 16 + lrow) * BSTR) * 2 + colOff;
                LDSM_X4(r0, r1, r2, r3, addr);
                bhi[2 * g][0] = r0; bhi[2 * g][1] = r2;
                bhi[2 * g + 1][0] = r1; bhi[2 * g + 1][1] = r3;
            }
            uint32_t a[4][4];
#pragma unroll
            for (int mt = 0; mt < 4; mt++) {
                uint32_t addr = uAH + ((uint32_t)(m0 + mt * 16 + lrow) * BSTR) * 2 + colOff;
                LDSM_X4(a[mt][0], a[mt][1], a[mt][2], a[mt][3], addr);
            }
#pragma unroll
            for (int mt = 0; mt < 4; mt++)
#pragma unroll
                for (int nt = 0; nt < 4; nt++)
                    mma_bf16(acc[mt][nt], a[mt][0], a[mt][1], a[mt][2], a[mt][3],
                             bhi[nt][0], bhi[nt][1]);
            uint32_t blo[4][2];
#pragma unroll
            for (int g = 0; g < 2; g++) {
                uint32_t r0, r1, r2, r3;
                uint32_t addr = uWL + ((uint32_t)(n0 + g * 16 + lrow) * BSTR) * 2 + colOff;
                LDSM_X4(r0, r1, r2, r3, addr);
                blo[2 * g][0] = r0; blo[2 * g][1] = r2;
                blo[2 * g + 1][0] = r1; blo[2 * g + 1][1] = r3;
            }
#pragma unroll
            for (int mt = 0; mt < 4; mt++)
#pragma unroll
                for (int nt = 0; nt < 4; nt++)
                    mma_bf16(acc[mt][nt], a[mt][0], a[mt][1], a[mt][2], a[mt][3],
                             blo[nt][0], blo[nt][1]);
#pragma unroll
            for (int mt = 0; mt < 4; mt++) {
                uint32_t addr = uAL + ((uint32_t)(m0 + mt * 16 + lrow) * BSTR) * 2 + colOff;
                LDSM_X4(a[mt][0], a[mt][1], a[mt][2], a[mt][3], addr);
            }
#pragma unroll
            for (int mt = 0; mt < 4; mt++)
#pragma unroll
                for (int nt = 0; nt < 4; nt++)
                    mma_bf16(acc[mt][nt], a[mt][0], a[mt][1], a[mt][2], a[mt][3],
                             bhi[nt][0], bhi[nt][1]);
        }

        float* C = Cj[j];
        const float* bias = bj[j];
#pragma unroll
        for (int nt = 0; nt < 4; nt++) {
            const int col = n0 + nt * 8 + cc2;
            const float bb0 = bias[col], bb1 = bias[col + 1];
            float s0 = 0.0f, s1 = 0.0f, q0 = 0.0f, q1 = 0.0f;
#pragma unroll
            for (int mt = 0; mt < 4; mt++) {
                const long r0 = rowBase + m0 + mt * 16 + cr;
                float x0 = acc[mt][nt][0] + bb0;
                float x1 = acc[mt][nt][1] + bb1;
                float x2 = acc[mt][nt][2] + bb0;
                float x3 = acc[mt][nt][3] + bb1;
                *(float2*)(C + r0 * 128 + col)       = make_float2(x0, x1);
                *(float2*)(C + (r0 + 8) * 128 + col) = make_float2(x2, x3);
                s0 += x0 + x2; s1 += x1 + x3;
                q0 += x0 * x0 + x2 * x2; q1 += x1 * x1 + x3 * x3;
            }
#pragma unroll
            for (int off = 4; off <= 16; off <<= 1) {
                s0 += __shfl_xor_sync(0xffffffffu, s0, off);
                s1 += __shfl_xor_sync(0xffffffffu, s1, off);
                q0 += __shfl_xor_sync(0xffffffffu, q0, off);
                q1 += __shfl_xor_sync(0xffffffffu, q1, off);
            }
            if (cr == 0) {
                atomicAdd(&sumj[j][col], s0);  atomicAdd(&sumj[j][col + 1], s1);
                atomicAdd(&sqj[j][col], q0);   atomicAdd(&sqj[j][col + 1], q1);
            }
        }
    }
}

// ================= Attention v5: P_lo aliases dead Q/K smem -> 2 CTAs/SM =================
#define QSTR 40
#define PSTR 136
#define AQH  0
#define AQL  5120
#define AKH  10240
#define AKL  15360
#define AVTH 20480
#define AVTL 24832
#define APH  29184
#define APL  0            // aliases Q/K region (dead after S mainloop)
#define AEND 46592
#define ATTN_SMEM (AEND * 2 + 7 * 128 * 4)   // 96768 B -> 2 CTAs/SM

__global__ void __launch_bounds__(256, 2)
attn_kernel(const float* __restrict__ q,
            const float* __restrict__ k,
            const float* __restrict__ v,
            const float* __restrict__ mask,
            const float* __restrict__ sumQ, const float* __restrict__ sqQ,
            const float* __restrict__ gQ, const float* __restrict__ bQ,
            const float* __restrict__ sumK, const float* __restrict__ sqK,
            const float* __restrict__ gK, const float* __restrict__ bK,
            const float* __restrict__ sumV, const float* __restrict__ sqV,
            const float* __restrict__ gV, const float* __restrict__ bV,
            float* __restrict__ out) {
    extern __shared__ __nv_bfloat16 smem[];
    float* aux = (float*)(smem + AEND);
    float* rowsum = aux;            // [128]
    float* scQ = aux + 128;  float* shQ = aux + 256;
    float* scK = aux + 384;  float* shK = aux + 512;
    float* scV = aux + 640;  float* shV = aux + 768;

    const int h = blockIdx.x;
    const int n = blockIdx.y;
    const int tid = threadIdx.x;
    const long base = (long)n * SS * DD + h * CC;
    const long mbase = (long)n * SS * SS;
    const int dBase = h * CC;

    if (tid < 128) {
        rowsum[tid] = 0.0f;
        bn_affine(sumQ, sqQ, gQ, bQ, tid, scQ[tid], shQ[tid]);
        bn_affine(sumV, sqV, gV, bV, tid, scV[tid], shV[tid]);
    } else {
        int c = tid - 128;
        bn_affine(sumK, sqK, gK, bK, c, scK[c], shK[c]);
    }
    __syncthreads();

    for (int idx = tid; idx < 1024; idx += 256) {
        int r = idx >> 3, c0 = (idx & 7) * 4;
        int d = dBase + c0;
        float4 s4 = *(const float4*)(scQ + d);
        float4 t4 = *(const float4*)(shQ + d);
        float4 x = *(const float4*)(q + base + (long)r * 128 + c0);
        x.x = x.x * s4.x + t4.x; x.y = x.y * s4.y + t4.y;
        x.z = x.z * s4.z + t4.z; x.w = x.w * s4.w + t4.w;
        float h0 = __bfloat162float(__float2bfloat16_rn(x.x));
        float h1 = __bfloat162float(__float2bfloat16_rn(x.y));
        float h2 = __bfloat162float(__float2bfloat16_rn(x.z));
        float h3 = __bfloat162float(__float2bfloat16_rn(x.w));
        *(uint2*)(smem + AQH + r * QSTR + c0) = make_uint2(packbf(x.x, x.y), packbf(x.z, x.w));
        *(uint2*)(smem + AQL + r * QSTR + c0) =
            make_uint2(packbf(x.x - h0, x.y - h1), packbf(x.z - h2, x.w - h3));

        s4 = *(const float4*)(scK + d);
        t4 = *(const float4*)(shK + d);
        x = *(const float4*)(k + base + (long)r * 128 + c0);
        x.x = x.x * s4.x + t4.x; x.y = x.y * s4.y + t4.y;
        x.z = x.z * s4.z + t4.z; x.w = x.w * s4.w + t4.w;
        h0 = __bfloat162float(__float2bfloat16_rn(x.x));
        h1 = __bfloat162float(__float2bfloat16_rn(x.y));
        h2 = __bfloat162float(__float2bfloat16_rn(x.z));
        h3 = __bfloat162float(__float2bfloat16_rn(x.w));
        *(uint2*)(smem + AKH + r * QSTR + c0) = make_uint2(packbf(x.x, x.y), packbf(x.z, x.w));
        *(uint2*)(smem + AKL + r * QSTR + c0) =
            make_uint2(packbf(x.x - h0, x.y - h1), packbf(x.z - h2, x.w - h3));
    }
    for (int idx = tid; idx < 1024; idx += 256) {
        int r = idx >> 3, c0 = (idx & 7) * 4;
        int d = dBase + c0;
        float4 s4 = *(const float4*)(scV + d);
        float4 t4 = *(const float4*)(shV + d);
        float4 x = *(const float4*)(v + base + (long)r * 128 + c0);
        float val[4];
        val[0] = x.x * s4.x + t4.x; val[1] = x.y * s4.y + t4.y;
        val[2] = x.z * s4.z + t4.z; val[3] = x.w * s4.w + t4.w;
#pragma unroll
        for (int j = 0; j < 4; j++) {
            __nv_bfloat16 hi = __float2bfloat16_rn(val[j]);
            smem[AVTH + (c0 + j) * PSTR + r] = hi;
            smem[AVTL + (c0 + j) * PSTR + r] =
                __float2bfloat16_rn(val[j] - __bfloat162float(hi));
        }
    }
    __syncthreads();

    const int warp = tid >> 5, lane = tid & 31;
    const int lrow = lane & 15, lhalf = (lane >> 4) * 8;
    const int cr = lane >> 2, cc2 = (lane & 3) * 2;

    const uint32_t uQH = smem_u32(smem + AQH), uQL = smem_u32(smem + AQL);
    const uint32_t uKH = smem_u32(smem + AKH), uKL = smem_u32(smem + AKL);

    // ======== S phase ========
    {
        const int wm = warp >> 2, wn = warp & 3;
        const int m0 = wm * 64, n0 = wn * 32;

        float acc[4][4][4];
#pragma unroll
        for (int mt = 0; mt < 4; mt++)
#pragma unroll
            for (int nt = 0; nt < 4; nt++)
#pragma unroll
                for (int i = 0; i < 4; i++) acc[mt][nt][i] = 0.0f;

#pragma unroll
        for (int ks = 0; ks < 2; ks++) {
            const uint32_t colOff = (uint32_t)(ks * 16 + lhalf) * 2;
            uint32_t bhi[4][2];
#pragma unroll
            for (int g = 0; g < 2; g++) {
                uint32_t r0, r1, r2, r3;
                uint32_t addr = uKH + ((uint32_t)(n0 + g * 16 + lrow) * QSTR) * 2 + colOff;
                LDSM_X4(r0, r1, r2, r3, addr);
                bhi[2 * g][0] = r0; bhi[2 * g][1] = r2;
                bhi[2 * g + 1][0] = r1; bhi[2 * g + 1][1] = r3;
            }
            uint32_t a[4][4];
#pragma unroll
            for (int mt = 0; mt < 4; mt++) {
                uint32_t addr = uQH + ((uint32_t)(m0 + mt * 16 + lrow) * QSTR) * 2 + colOff;
                LDSM_X4(a[mt][0], a[mt][1], a[mt][2], a[mt][3], addr);
            }
#pragma unroll
            for (int mt = 0; mt < 4; mt++)
#pragma unroll
                for (int nt = 0; nt < 4; nt++)
                    mma_bf16(acc[mt][nt], a[mt][0], a[mt][1], a[mt][2], a[mt][3],
                             bhi[nt][0], bhi[nt][1]);
            uint32_t blo[4][2];
#pragma unroll
            for (int g = 0; g < 2; g++) {
                uint32_t r0, r1, r2, r3;
                uint32_t addr = uKL + ((uint32_t)(n0 + g * 16 + lrow) * QSTR) * 2 + colOff;
                LDSM_X4(r0, r1, r2, r3, addr);
                blo[2 * g][0] = r0; blo[2 * g][1] = r2;
                blo[2 * g + 1][0] = r1; blo[2 * g + 1][1] = r3;
            }
#pragma unroll
            for (int mt = 0; mt < 4; mt++)
#pragma unroll
                for (int nt = 0; nt < 4; nt++)
                    mma_bf16(acc[mt][nt], a[mt][0], a[mt][1], a[mt][2], a[mt][3],
                             blo[nt][0], blo[nt][1]);
#pragma unroll
            for (int mt = 0; mt < 4; mt++) {
                uint32_t addr = uQL + ((uint32_t)(m0 + mt * 16 + lrow) * QSTR) * 2 + colOff;
                LDSM_X4(a[mt][0], a[mt][1], a[mt][2], a[mt][3], addr);
            }
#pragma unroll
            for (int mt = 0; mt < 4; mt++)
#pragma unroll
                for (int nt = 0; nt < 4; nt++)
                    mma_bf16(acc[mt][nt], a[mt][0], a[mt][1], a[mt][2], a[mt][3],
                             bhi[nt][0], bhi[nt][1]);
        }

        // ALL warps must finish reading Q/K before P_lo overwrites that region
        __syncthreads();

#pragma unroll
        for (int mt = 0; mt < 4; mt++) {
            const int row0 = m0 + mt * 16 + cr;
            float s0 = 0.0f, s1 = 0.0f;
#pragma unroll
            for (int nt = 0; nt < 4; nt++) {
                const int col = n0 + nt * 8 + cc2;
                float2 mv0 = *(const float2*)(mask + mbase + (long)row0 * 128 + col);
                float2 mv1 = *(const float2*)(mask + mbase + (long)(row0 + 8) * 128 + col);
                float p00 = __expf(acc[mt][nt][0] * mv0.x);
                float p01 = __expf(acc[mt][nt][1] * mv0.y);
                float p10 = __expf(acc[mt][nt][2] * mv1.x);
                float p11 = __expf(acc[mt][nt][3] * mv1.y);
                s0 += p00 + p01;
                s1 += p10 + p11;
                __nv_bfloat16 h00 = __float2bfloat16_rn(p00);
                __nv_bfloat16 h01 = __float2bfloat16_rn(p01);
                __nv_bfloat16 h10 = __float2bfloat16_rn(p10);
                __nv_bfloat16 h11 = __float2bfloat16_rn(p11);
                *(uint32_t*)(smem + APH + row0 * PSTR + col) =
                    packbf(__bfloat162float(h00), __bfloat162float(h01));
                *(uint32_t*)(smem + APH + (row0 + 8) * PSTR + col) =
                    packbf(__bfloat162float(h10), __bfloat162float(h11));
                *(uint32_t*)(smem + APL + row0 * PSTR + col) =
                    packbf(p00 - __bfloat162float(h00), p01 - __bfloat162float(h01));
                *(uint32_t*)(smem + APL + (row0 + 8) * PSTR + col) =
                    packbf(p10 - __bfloat162float(h10), p11 - __bfloat162float(h11));
            }
            s0 += __shfl_xor_sync(0xffffffffu, s0, 1);
            s0 += __shfl_xor_sync(0xffffffffu, s0, 2);
            s1 += __shfl_xor_sync(0xffffffffu, s1, 1);
            s1 += __shfl_xor_sync(0xffffffffu, s1, 2);
            if ((lane & 3) == 0) {
                atomicAdd(&rowsum[row0], s0);
                atomicAdd(&rowsum[row0 + 8], s1);
            }
        }
    }
    __syncthreads();

    // ======== PV phase: 3 passes (Phi*Vhi + Phi*Vlo + Plo*Vhi) ========
    {
        const int m0 = warp * 16;
        const uint32_t uPH = smem_u32(smem + APH), uPL = smem_u32(smem + APL);
        const uint32_t uVH = smem_u32(smem + AVTH), uVL = smem_u32(smem + AVTL);

        float acc[4][4];
#pragma unroll
        for (int nt = 0; nt < 4; nt++)
#pragma unroll
            for (int i = 0; i < 4; i++) acc[nt][i] = 0.0f;

#pragma unroll
        for (int ks = 0; ks < 8; ks++) {
            const uint32_t colOff = (uint32_t)(ks * 16 + lhalf) * 2;
            uint32_t bhi[4][2];
#pragma unroll
            for (int g = 0; g < 2; g++) {
                uint32_t r0, r1, r2, r3;
                uint32_t addr = uVH + ((uint32_t)(g * 16 + lrow) * PSTR) * 2 + colOff;
                LDSM_X4(r0, r1, r2, r3, addr);
                bhi[2 * g][0] = r0; bhi[2 * g][1] = r2;
                bhi[2 * g + 1][0] = r1; bhi[2 * g + 1][1] = r3;
            }
            uint32_t a[4];
            {
                uint32_t addr = uPH + ((uint32_t)(m0 + lrow) * PSTR) * 2 + colOff;
                LDSM_X4(a[0], a[1], a[2], a[3], addr);
            }
#pragma unroll
            for (int nt = 0; nt < 4; nt++)
                mma_bf16(acc[nt], a[0], a[1], a[2], a[3], bhi[nt][0], bhi[nt][1]);
            uint32_t blo[4][2];
#pragma unroll
            for (int g = 0; g < 2; g++) {
                uint32_t r0, r1, r2, r3;
                uint32_t addr = uVL + ((uint32_t)(g * 16 + lrow) * PSTR) * 2 + colOff;
                LDSM_X4(r0, r1, r2, r3, addr);
                blo[2 * g][0] = r0; blo[2 * g][1] = r2;
                blo[2 * g + 1][0] = r1; blo[2 * g + 1][1] = r3;
            }
#pragma unroll
            for (int nt = 0; nt < 4; nt++)
                mma_bf16(acc[nt], a[0], a[1], a[2], a[3], blo[nt][0], blo[nt][1]);
            {
                uint32_t addr = uPL + ((uint32_t)(m0 + lrow) * PSTR) * 2 + colOff;
                LDSM_X4(a[0], a[1], a[2], a[3], addr);
            }
#pragma unroll
            for (int nt = 0; nt < 4; nt++)
                mma_bf16(acc[nt], a[0], a[1], a[2], a[3], bhi[nt][0], bhi[nt][1]);
        }

        const int row0 = m0 + cr;
        const float inv0 = 1.0f / rowsum[row0];
        const float inv1 = 1.0f / rowsum[row0 + 8];
#pragma unroll
        for (int nt = 0; nt < 4; nt++) {
            const int col = nt * 8 + cc2;
            *(float2*)(out + base + (long)row0 * 128 + col) =
                make_float2(acc[nt][0] * inv0, acc[nt][1] * inv0);
            *(float2*)(out + base + (long)(row0 + 8) * 128 + col) =
                make_float2(acc[nt][2] * inv1, acc[nt][3] * inv1);
        }
    }
}

// ---------------- out = LayerNorm(A + affine(B)) per row (affine from raw stats) ----------------
__global__ void add_ln_kernel(const float* __restrict__ A,
                              const float* __restrict__ B,
                              const float* __restrict__ sumB, const float* __restrict__ sqB,
                              const float* __restrict__ gB, const float* __restrict__ bB,
                              const float* __restrict__ gam,
                              const float* __restrict__ bet,
                              float* __restrict__ Out) {
    __shared__ float sc[128], sh[128];
    const int tid = threadIdx.x;
    if (tid < 128) {
        if (gB) bn_affine(sumB, sqB, gB, bB, tid, sc[tid], sh[tid]);
        else { sc[tid] = 1.0f; sh[tid] = 0.0f; }
    }
    __syncthreads();

    const int w = tid >> 5, lane = tid & 31;
    const long row = (long)blockIdx.x * 8 + w;
    const float* a = A + row * 128;
    const float* b = B + row * 128;

    float x[4];
    float s = 0.0f, s2 = 0.0f;
#pragma unroll
    for (int i = 0; i < 4; i++) {
        int c = lane + 32 * i;
        x[i] = a[c] + b[c] * sc[c] + sh[c];
        s += x[i];
        s2 += x[i] * x[i];
    }
#pragma unroll
    for (int o = 16; o > 0; o >>= 1) {
        s  += __shfl_xor_sync(0xffffffffu, s, o);
        s2 += __shfl_xor_sync(0xffffffffu, s2, o);
    }
    const float m = s * (1.0f / 128.0f);
    const float var = s2 * (1.0f / 128.0f) - m * m;
    const float r = rsqrtf(var + EPS);
#pragma unroll
    for (int i = 0; i < 4; i++) {
        int c = lane + 32 * i;
        Out[row * 128 + c] = (x[i] - m) * r * gam[c] + bet[c];
    }
}

// ---------------- h = LN(O + affine_ff(F)) + affine_sk(S); optional fused gather ----------------
__global__ void ln_add_affine_kernel(const float* __restrict__ O,
                                     const float* __restrict__ F,
                                     const float* __restrict__ sumF, const float* __restrict__ sqF,
                                     const float* __restrict__ gF, const float* __restrict__ bF,
                                     const float* __restrict__ Sk,
                                     const float* __restrict__ sumS, const float* __restrict__ sqS,
                                     const float* __restrict__ gS, const float* __restrict__ bS,
                                     const float* __restrict__ gam,
                                     const float* __restrict__ bet,
                                     float* __restrict__ Out,
                                     float* __restrict__ gatherOut) {
    __shared__ float sc4[128], sh4[128], sc5[128], sh5[128];
    const int tid = threadIdx.x;
    if (tid < 128) {
        bn_affine(sumF, sqF, gF, bF, tid, sc4[tid], sh4[tid]);
    } else {
        int c = tid - 128;
        bn_affine(sumS, sqS, gS, bS, c, sc5[c], sh5[c]);
    }
    __syncthreads();

    const int w = tid >> 5, lane = tid & 31;
    const long row = (long)blockIdx.x * 8 + w;
    const float* o = O + row * 128;
    const float* f = F + row * 128;
    const float* sk = Sk + row * 128;

    float x[4];
    float s = 0.0f, s2 = 0.0f;
#pragma unroll
    for (int i = 0; i < 4; i++) {
        int c = lane + 32 * i;
        x[i] = o[c] + f[c] * sc4[c] + sh4[c];
        s += x[i];
        s2 += x[i] * x[i];
    }
#pragma unroll
    for (int off = 16; off > 0; off >>= 1) {
        s  += __shfl_xor_sync(0xffffffffu, s, off);
        s2 += __shfl_xor_sync(0xffffffffu, s2, off);
    }
    const float m = s * (1.0f / 128.0f);
    const float var = s2 * (1.0f / 128.0f) - m * m;
    const float r = rsqrtf(var + EPS);
    const bool doGather = (gatherOut != 0) && ((row & 127) == 0);
#pragma unroll
    for (int i = 0; i < 4; i++) {
        int c = lane + 32 * i;
        float val = (x[i] - m) * r * gam[c] + bet[c] + sk[c] * sc5[c] + sh5[c];
        Out[row * 128 + c] = val;
        if (doGather) gatherOut[(row >> 7) * 128 + c] = val;
    }
}

// ---------------- host orchestration ----------------
extern "C" void kernel_launch(void* const* d_in, const int* in_sizes, int n_in,
                              void* d_out, int out_size) {
    const float* x        = (const float*)d_in[0];
    const float* mask     = (const float*)d_in[1];
    const float* lin_in_W = (const float*)d_in[2];
    const float* lin_in_b = (const float*)d_in[3];
    const float* in_bn_g  = (const float*)d_in[4];
    const float* in_bn_b  = (const float*)d_in[5];
    const float* q_W      = (const float*)d_in[6];
    const float* q_b      = (const float*)d_in[7];
    const float* q_bn_g   = (const float*)d_in[8];
    const float* q_bn_b   = (const float*)d_in[9];
    const float* k_W      = (const float*)d_in[10];
    const float* k_b      = (const float*)d_in[11];
    const float* k_bn_g   = (const float*)d_in[12];
    const float* k_bn_b   = (const float*)d_in[13];
    const float* v_W      = (const float*)d_in[14];
    const float* v_b      = (const float*)d_in[15];
    const float* v_bn_g   = (const float*)d_in[16];
    const float* v_bn_b   = (const float*)d_in[17];
    const float* ln_g     = (const float*)d_in[18];
    const float* ln_b     = (const float*)d_in[19];
    const float* ff_W     = (const float*)d_in[20];
    const float* ff_b     = (const float*)d_in[21];
    const float* ff_bn_g  = (const float*)d_in[22];
    const float* ff_bn_b  = (const float*)d_in[23];
    const float* skip_W   = (const float*)d_in[24];
    const float* skip_b   = (const float*)d_in[25];
    const float* skip_bn_g= (const float*)d_in[26];
    const float* skip_bn_b= (const float*)d_in[27];
    float* out = (float*)d_out;

    cudaFuncSetAttribute(gemm_tc_kernel, cudaFuncAttributeMaxDynamicSharedMemorySize, GEMM_SMEM);
    cudaFuncSetAttribute(attn_kernel, cudaFuncAttributeMaxDynamicSharedMemorySize, ATTN_SMEM);

    float *bh, *bt, *bq, *bk, *bv, *bs, *ba, *bo, *bf, *bsum, *bsq;
    cudaGetSymbolAddress((void**)&bh, g_h);
    cudaGetSymbolAddress((void**)&bt, g_t);
    cudaGetSymbolAddress((void**)&bq, g_q);
    cudaGetSymbolAddress((void**)&bk, g_k);
    cudaGetSymbolAddress((void**)&bv, g_v);
    cudaGetSymbolAddress((void**)&bs, g_s);
    cudaGetSymbolAddress((void**)&ba, g_a);
    cudaGetSymbolAddress((void**)&bo, g_o);
    cudaGetSymbolAddress((void**)&bf, g_f);
    cudaGetSymbolAddress((void**)&bsum, g_stat_sum);
    cudaGetSymbolAddress((void**)&bsq, g_stat_sq);

    auto SUM = [&](int i) { return bsum + i * DD; };
    auto SQ  = [&](int i) { return bsq + i * DD; };

    const int GEMM_GRID = M_ROWS / 256;   // 512

    // launch 1: zero all stat slots
    zero_stats_kernel<<<(NSLOT * DD + 255) / 256, 256>>>();

    // launch 2: t0 = x @ Win^T + b ; stats -> slot 0
    gemm_tc_kernel<<<GEMM_GRID, 512, GEMM_SMEM>>>(
        x, 0, 0, 0, 0,
        lin_in_W, lin_in_W, lin_in_W, lin_in_W,
        lin_in_b, lin_in_b, lin_in_b, lin_in_b,
        bt, bt, bt, bt,
        SUM(0), SUM(0), SUM(0), SUM(0), SQ(0), SQ(0), SQ(0), SQ(0), 1);

    // launch 3: spacer so the profiler's fixed slot (#4) captures the QKVS GEMM
    noop_kernel<<<1, 32>>>();

    for (int l = 0; l < LL; l++) {
        const long wOff = (long)l * DD * DD;
        const long vOff = (long)l * DD;
        const float* hp = (l == 0) ? bt : bh;
        const int sq_ = 1 + l * 5, sk_ = 2 + l * 5, sv_ = 3 + l * 5,
                  ss_ = 4 + l * 5, sf_ = 5 + l * 5;
        const float* hSum = (l == 0) ? SUM(0) : 0;
        const float* hSq  = (l == 0) ? SQ(0) : 0;
        const float* hG   = (l == 0) ? in_bn_g : 0;
        const float* hB   = (l == 0) ? in_bn_b : 0;

        // fused Q/K/V/skip GEMM (launch 4 for l=0 — ncu target)
        gemm_tc_kernel<<<GEMM_GRID, 512, GEMM_SMEM>>>(
            hp, hSum, hSq, hG, hB,
            q_W + wOff, k_W + wOff, v_W + wOff, skip_W + wOff,
            q_b + vOff, k_b + vOff, v_b + vOff, skip_b + vOff,
            bq, bk, bv, bs,
            SUM(sq_), SUM(sk_), SUM(sv_), SUM(ss_),
            SQ(sq_), SQ(sk_), SQ(sv_), SQ(ss_), 4);

        // attention
        dim3 agrid(HH, NB);
        attn_kernel<<<agrid, 256, ATTN_SMEM>>>(
            bq, bk, bv, mask,
            SUM(sq_), SQ(sq_), q_bn_g + vOff, q_bn_b + vOff,
            SUM(sk_), SQ(sk_), k_bn_g + vOff, k_bn_b + vOff,
            SUM(sv_), SQ(sv_), v_bn_g + vOff, v_bn_b + vOff,
            ba);

        // out = LN(agg + h)
        add_ln_kernel<<<M_ROWS / 8, 256>>>(ba, hp, hSum, hSq, hG, hB,
                                           ln_g + vOff, ln_b + vOff, bo);

        // ff GEMM -> slot sf_
        gemm_tc_kernel<<<GEMM_GRID, 512, GEMM_SMEM>>>(
            bo, 0, 0, 0, 0,
            ff_W + wOff, ff_W + wOff, ff_W + wOff, ff_W + wOff,
            ff_b + vOff, ff_b + vOff, ff_b + vOff, ff_b + vOff,
            bf, bf, bf, bf,
            SUM(sf_), SUM(sf_), SUM(sf_), SUM(sf_),
            SQ(sf_), SQ(sf_), SQ(sf_), SQ(sf_), 1);

        // h = LN(out + affine_ff(ff)) + affine_skip(skip)  [+ fused gather on last layer]
        ln_add_affine_kernel<<<M_ROWS / 8, 256>>>(
            bo, bf, SUM(sf_), SQ(sf_), ff_bn_g + vOff, ff_bn_b + vOff,
            bs, SUM(ss_), SQ(ss_), skip_bn_g + vOff, skip_bn_b + vOff,
            ln_g + vOff, ln_b + vOff, bh,
            (l == LL - 1) ? out : 0);
    }
}

// round 14
// speedup vs baseline: 1.0006x; 1.0006x over previous
#include <cuda_runtime.h>
#include <cuda_bf16.h>
#include <math.h>
#include <stdint.h>

// ---------------- problem constants ----------------
#define NB      1024
#define SS      128
#define DD      128
#define HH      4
#define CC      32
#define LL      2
#define M_ROWS  (NB * SS)
#define MSZ     (M_ROWS * DD)
#define EPS     1e-5f
#define INV_M   (1.0f / (float)M_ROWS)
#define NSLOT   11

// ---------------- scratch ----------------
__device__ float g_h[MSZ];
__device__ float g_t[MSZ];
__device__ float g_q[MSZ];
__device__ float g_k[MSZ];
__device__ float g_v[MSZ];
__device__ float g_s[MSZ];
__device__ float g_a[MSZ];
__device__ float g_o[MSZ];
__device__ float g_f[MSZ];
__device__ float g_stat_sum[NSLOT][DD];
__device__ float g_stat_sq[NSLOT][DD];

// ================= helpers =================
__device__ __forceinline__ uint32_t smem_u32(const void* p) {
    uint32_t a;
    asm("{ .reg .u64 t; cvta.to.shared.u64 t, %1; cvt.u32.u64 %0, t; }" : "=r"(a) : "l"(p));
    return a;
}
__device__ __forceinline__ uint32_t packbf(float a, float b) {
    __nv_bfloat162 t = __floats2bfloat162_rn(a, b);
    return *(uint32_t*)&t;
}
__device__ __forceinline__ void bn_affine(const float* sum, const float* sq,
                                          const float* g, const float* b, int c,
                                          float& sc, float& sh) {
    float m = sum[c] * INV_M;
    float var = sq[c] * INV_M - m * m;
    float s = g[c] * rsqrtf(var + EPS);
    sc = s;
    sh = b[c] - m * s;
}

#define LDSM_X4(r0, r1, r2, r3, addr) \
    asm volatile("ldmatrix.sync.aligned.m8n8.x4.shared.b16 {%0,%1,%2,%3}, [%4];" \
                 : "=r"(r0), "=r"(r1), "=r"(r2), "=r"(r3) : "r"(addr))

__device__ __forceinline__ void mma_bf16(float c[4],
                                         uint32_t a0, uint32_t a1, uint32_t a2, uint32_t a3,
                                         uint32_t b0, uint32_t b1) {
    asm volatile(
        "mma.sync.aligned.m16n8k16.row.col.f32.bf16.bf16.f32 "
        "{%0,%1,%2,%3}, {%4,%5,%6,%7}, {%8,%9}, {%0,%1,%2,%3};"
        : "+f"(c[0]), "+f"(c[1]), "+f"(c[2]), "+f"(c[3])
        : "r"(a0), "r"(a1), "r"(a2), "r"(a3), "r"(b0), "r"(b1));
}

// ---------------- zero all stat slots (start of graph) ----------------
__global__ void zero_stats_kernel() {
    int i = blockIdx.x * blockDim.x + threadIdx.x;
    if (i < NSLOT * DD) {
        ((float*)g_stat_sum)[i] = 0.0f;
        ((float*)g_stat_sq)[i] = 0.0f;
    }
}

// ---------------- no-op spacer: keeps profiler capture slot on the QKVS GEMM ----------------
__global__ void noop_kernel() {}

// ================= GEMM v3: 128-row tile, warp tile 32x32 (low reg pressure) =================
// Up to 4 weight sets share one converted A tile. 512 threads, warp grid 4x4.
#define BSTR 136
#define A_TILE_E (128 * BSTR)
#define W_TILE_E (128 * BSTR)
#define GEMM_SMEM ((2 * A_TILE_E + 2 * W_TILE_E) * 2 + 1024)   // 140288 B

__global__ void __launch_bounds__(512)
gemm_tc_kernel(const float* __restrict__ A,
               const float* __restrict__ sumA, const float* __restrict__ sqA,
               const float* __restrict__ gA, const float* __restrict__ bA,
               const float* W0, const float* W1, const float* W2, const float* W3,
               const float* b0, const float* b1, const float* b2, const float* b3,
               float* C0, float* C1, float* C2, float* C3,
               float* sum0, float* sum1, float* sum2, float* sum3,
               float* sq0, float* sq1, float* sq2, float* sq3,
               int nW) {
    extern __shared__ __nv_bfloat16 smem[];
    __nv_bfloat16* AH = smem;
    __nv_bfloat16* AL = smem + A_TILE_E;
    __nv_bfloat16* WH = smem + 2 * A_TILE_E;
    __nv_bfloat16* WL = smem + 2 * A_TILE_E + W_TILE_E;
    float* sAff = (float*)(smem + 2 * A_TILE_E + 2 * W_TILE_E);   // [256]

    const float* Wj[4] = {W0, W1, W2, W3};
    const float* bj[4] = {b0, b1, b2, b3};
    float* Cj[4] = {C0, C1, C2, C3};
    float* sumj[4] = {sum0, sum1, sum2, sum3};
    float* sqj[4] = {sq0, sq1, sq2, sq3};

    const int tid = threadIdx.x;
    const long rowBase = (long)blockIdx.x * 128;

    if (gA && tid < 128) {
        float sc, sh;
        bn_affine(sumA, sqA, gA, bA, tid, sc, sh);
        sAff[tid] = sc;
        sAff[128 + tid] = sh;
    }
    __syncthreads();

    // ---- fill A_hi / A_lo (128 rows) ----
    for (int idx = tid; idx < 4096; idx += 512) {
        int r = idx >> 5, k0 = (idx & 31) * 4;
        float4 v = *(const float4*)(A + (rowBase + r) * 128 + k0);
        if (gA) {
            float4 s = *(const float4*)(sAff + k0);
            float4 t = *(const float4*)(sAff + 128 + k0);
            v.x = v.x * s.x + t.x; v.y = v.y * s.y + t.y;
            v.z = v.z * s.z + t.z; v.w = v.w * s.w + t.w;
        }
        float h0 = __bfloat162float(__float2bfloat16_rn(v.x));
        float h1 = __bfloat162float(__float2bfloat16_rn(v.y));
        float h2 = __bfloat162float(__float2bfloat16_rn(v.z));
        float h3 = __bfloat162float(__float2bfloat16_rn(v.w));
        *(uint2*)(AH + r * BSTR + k0) = make_uint2(packbf(v.x, v.y), packbf(v.z, v.w));
        *(uint2*)(AL + r * BSTR + k0) =
            make_uint2(packbf(v.x - h0, v.y - h1), packbf(v.z - h2, v.w - h3));
    }

    const int warp = tid >> 5, lane = tid & 31;
    const int wm = warp >> 2, wn = warp & 3;       // 4 x 4 warp grid
    const int m0 = wm * 32, n0 = wn * 32;          // warp tile 32x32
    const int lrow = lane & 15, lhalf = (lane >> 4) * 8;
    const int cr = lane >> 2, cc2 = (lane & 3) * 2;

    const uint32_t uAH = smem_u32(AH), uAL = smem_u32(AL);
    const uint32_t uWH = smem_u32(WH), uWL = smem_u32(WL);

    for (int j = 0; j < nW; j++) {
        if (j > 0) __syncthreads();
        const float* W = Wj[j];
        for (int idx = tid; idx < 4096; idx += 512) {
            int r = idx >> 5, k0 = (idx & 31) * 4;
            float4 v = *(const float4*)(W + r * 128 + k0);
            float h0 = __bfloat162float(__float2bfloat16_rn(v.x));
            float h1 = __bfloat162float(__float2bfloat16_rn(v.y));
            float h2 = __bfloat162float(__float2bfloat16_rn(v.z));
            float h3 = __bfloat162float(__float2bfloat16_rn(v.w));
            *(uint2*)(WH + r * BSTR + k0) = make_uint2(packbf(v.x, v.y), packbf(v.z, v.w));
            *(uint2*)(WL + r * BSTR + k0) =
                make_uint2(packbf(v.x - h0, v.y - h1), packbf(v.z - h2, v.w - h3));
        }
        __syncthreads();

        float acc[2][4][4];
#pragma unroll
        for (int mt = 0; mt < 2; mt++)
#pragma unroll
            for (int nt = 0; nt < 4; nt++)
#pragma unroll
                for (int i = 0; i < 4; i++) acc[mt][nt][i] = 0.0f;

#pragma unroll
        for (int ks = 0; ks < 8; ks++) {
            const uint32_t colOff = (uint32_t)(ks * 16 + lhalf) * 2;
            uint32_t bhi[4][2];
#pragma unroll
            for (int g = 0; g < 2; g++) {
                uint32_t r0, r1, r2, r3;
                uint32_t addr = uWH + ((uint32_t)(n0 + g * 16 + lrow) * BSTR) * 2 + colOff;
                LDSM_X4(r0, r1, r2, r3, addr);
                bhi[2 * g][0] = r0; bhi[2 * g][1] = r2;
                bhi[2 * g + 1][0] = r1; bhi[2 * g + 1][1] = r3;
            }
            uint32_t a[2][4];
#pragma unroll
            for (int mt = 0; mt < 2; mt++) {
                uint32_t addr = uAH + ((uint32_t)(m0 + mt * 16 + lrow) * BSTR) * 2 + colOff;
                LDSM_X4(a[mt][0], a[mt][1], a[mt][2], a[mt][3], addr);
            }
#pragma unroll
            for (int mt = 0; mt < 2; mt++)
#pragma unroll
                for (int nt = 0; nt < 4; nt++)
                    mma_bf16(acc[mt][nt], a[mt][0], a[mt][1], a[mt][2], a[mt][3],
                             bhi[nt][0], bhi[nt][1]);
            uint32_t blo[4][2];
#pragma unroll
            for (int g = 0; g < 2; g++) {
                uint32_t r0, r1, r2, r3;
                uint32_t addr = uWL + ((uint32_t)(n0 + g * 16 + lrow) * BSTR) * 2 + colOff;
                LDSM_X4(r0, r1, r2, r3, addr);
                blo[2 * g][0] = r0; blo[2 * g][1] = r2;
                blo[2 * g + 1][0] = r1; blo[2 * g + 1][1] = r3;
            }
#pragma unroll
            for (int mt = 0; mt < 2; mt++)
#pragma unroll
                for (int nt = 0; nt < 4; nt++)
                    mma_bf16(acc[mt][nt], a[mt][0], a[mt][1], a[mt][2], a[mt][3],
                             blo[nt][0], blo[nt][1]);
#pragma unroll
            for (int mt = 0; mt < 2; mt++) {
                uint32_t addr = uAL + ((uint32_t)(m0 + mt * 16 + lrow) * BSTR) * 2 + colOff;
                LDSM_X4(a[mt][0], a[mt][1], a[mt][2], a[mt][3], addr);
            }
#pragma unroll
            for (int mt = 0; mt < 2; mt++)
#pragma unroll
                for (int nt = 0; nt < 4; nt++)
                    mma_bf16(acc[mt][nt], a[mt][0], a[mt][1], a[mt][2], a[mt][3],
                             bhi[nt][0], bhi[nt][1]);
        }

        float* C = Cj[j];
        const float* bias = bj[j];
#pragma unroll
        for (int nt = 0; nt < 4; nt++) {
            const int col = n0 + nt * 8 + cc2;
            const float bb0 = bias[col], bb1 = bias[col + 1];
            float s0 = 0.0f, s1 = 0.0f, q0 = 0.0f, q1 = 0.0f;
#pragma unroll
            for (int mt = 0; mt < 2; mt++) {
                const long r0 = rowBase + m0 + mt * 16 + cr;
                float x0 = acc[mt][nt][0] + bb0;
                float x1 = acc[mt][nt][1] + bb1;
                float x2 = acc[mt][nt][2] + bb0;
                float x3 = acc[mt][nt][3] + bb1;
                *(float2*)(C + r0 * 128 + col)       = make_float2(x0, x1);
                *(float2*)(C + (r0 + 8) * 128 + col) = make_float2(x2, x3);
                s0 += x0 + x2; s1 += x1 + x3;
                q0 += x0 * x0 + x2 * x2; q1 += x1 * x1 + x3 * x3;
            }
#pragma unroll
            for (int off = 4; off <= 16; off <<= 1) {
                s0 += __shfl_xor_sync(0xffffffffu, s0, off);
                s1 += __shfl_xor_sync(0xffffffffu, s1, off);
                q0 += __shfl_xor_sync(0xffffffffu, q0, off);
                q1 += __shfl_xor_sync(0xffffffffu, q1, off);
            }
            if (cr == 0) {
                atomicAdd(&sumj[j][col], s0);  atomicAdd(&sumj[j][col + 1], s1);
                atomicAdd(&sqj[j][col], q0);   atomicAdd(&sqj[j][col + 1], q1);
            }
        }
    }
}

// ================= Attention v5: P_lo aliases dead Q/K smem -> 2 CTAs/SM =================
#define QSTR 40
#define PSTR 136
#define AQH  0
#define AQL  5120
#define AKH  10240
#define AKL  15360
#define AVTH 20480
#define AVTL 24832
#define APH  29184
#define APL  0            // aliases Q/K region (dead after S mainloop)
#define AEND 46592
#define ATTN_SMEM (AEND * 2 + 7 * 128 * 4)   // 96768 B -> 2 CTAs/SM

__global__ void __launch_bounds__(256, 2)
attn_kernel(const float* __restrict__ q,
            const float* __restrict__ k,
            const float* __restrict__ v,
            const float* __restrict__ mask,
            const float* __restrict__ sumQ, const float* __restrict__ sqQ,
            const float* __restrict__ gQ, const float* __restrict__ bQ,
            const float* __restrict__ sumK, const float* __restrict__ sqK,
            const float* __restrict__ gK, const float* __restrict__ bK,
            const float* __restrict__ sumV, const float* __restrict__ sqV,
            const float* __restrict__ gV, const float* __restrict__ bV,
            float* __restrict__ out) {
    extern __shared__ __nv_bfloat16 smem[];
    float* aux = (float*)(smem + AEND);
    float* rowsum = aux;            // [128]
    float* scQ = aux + 128;  float* shQ = aux + 256;
    float* scK = aux + 384;  float* shK = aux + 512;
    float* scV = aux + 640;  float* shV = aux + 768;

    const int h = blockIdx.x;
    const int n = blockIdx.y;
    const int tid = threadIdx.x;
    const long base = (long)n * SS * DD + h * CC;
    const long mbase = (long)n * SS * SS;
    const int dBase = h * CC;

    if (tid < 128) {
        rowsum[tid] = 0.0f;
        bn_affine(sumQ, sqQ, gQ, bQ, tid, scQ[tid], shQ[tid]);
        bn_affine(sumV, sqV, gV, bV, tid, scV[tid], shV[tid]);
    } else {
        int c = tid - 128;
        bn_affine(sumK, sqK, gK, bK, c, scK[c], shK[c]);
    }
    __syncthreads();

    for (int idx = tid; idx < 1024; idx += 256) {
        int r = idx >> 3, c0 = (idx & 7) * 4;
        int d = dBase + c0;
        float4 s4 = *(const float4*)(scQ + d);
        float4 t4 = *(const float4*)(shQ + d);
        float4 x = *(const float4*)(q + base + (long)r * 128 + c0);
        x.x = x.x * s4.x + t4.x; x.y = x.y * s4.y + t4.y;
        x.z = x.z * s4.z + t4.z; x.w = x.w * s4.w + t4.w;
        float h0 = __bfloat162float(__float2bfloat16_rn(x.x));
        float h1 = __bfloat162float(__float2bfloat16_rn(x.y));
        float h2 = __bfloat162float(__float2bfloat16_rn(x.z));
        float h3 = __bfloat162float(__float2bfloat16_rn(x.w));
        *(uint2*)(smem + AQH + r * QSTR + c0) = make_uint2(packbf(x.x, x.y), packbf(x.z, x.w));
        *(uint2*)(smem + AQL + r * QSTR + c0) =
            make_uint2(packbf(x.x - h0, x.y - h1), packbf(x.z - h2, x.w - h3));

        s4 = *(const float4*)(scK + d);
        t4 = *(const float4*)(shK + d);
        x = *(const float4*)(k + base + (long)r * 128 + c0);
        x.x = x.x * s4.x + t4.x; x.y = x.y * s4.y + t4.y;
        x.z = x.z * s4.z + t4.z; x.w = x.w * s4.w + t4.w;
        h0 = __bfloat162float(__float2bfloat16_rn(x.x));
        h1 = __bfloat162float(__float2bfloat16_rn(x.y));
        h2 = __bfloat162float(__float2bfloat16_rn(x.z));
        h3 = __bfloat162float(__float2bfloat16_rn(x.w));
        *(uint2*)(smem + AKH + r * QSTR + c0) = make_uint2(packbf(x.x, x.y), packbf(x.z, x.w));
        *(uint2*)(smem + AKL + r * QSTR + c0) =
            make_uint2(packbf(x.x - h0, x.y - h1), packbf(x.z - h2, x.w - h3));
    }
    for (int idx = tid; idx < 1024; idx += 256) {
        int r = idx >> 3, c0 = (idx & 7) * 4;
        int d = dBase + c0;
        float4 s4 = *(const float4*)(scV + d);
        float4 t4 = *(const float4*)(shV + d);
        float4 x = *(const float4*)(v + base + (long)r * 128 + c0);
        float val[4];
        val[0] = x.x * s4.x + t4.x; val[1] = x.y * s4.y + t4.y;
        val[2] = x.z * s4.z + t4.z; val[3] = x.w * s4.w + t4.w;
#pragma unroll
        for (int j = 0; j < 4; j++) {
            __nv_bfloat16 hi = __float2bfloat16_rn(val[j]);
            smem[AVTH + (c0 + j) * PSTR + r] = hi;
            smem[AVTL + (c0 + j) * PSTR + r] =
                __float2bfloat16_rn(val[j] - __bfloat162float(hi));
        }
    }
    __syncthreads();

    const int warp = tid >> 5, lane = tid & 31;
    const int lrow = lane & 15, lhalf = (lane >> 4) * 8;
    const int cr = lane >> 2, cc2 = (lane & 3) * 2;

    const uint32_t uQH = smem_u32(smem + AQH), uQL = smem_u32(smem + AQL);
    const uint32_t uKH = smem_u32(smem + AKH), uKL = smem_u32(smem + AKL);

    // ======== S phase ========
    {
        const int wm = warp >> 2, wn = warp & 3;
        const int m0 = wm * 64, n0 = wn * 32;

        float acc[4][4][4];
#pragma unroll
        for (int mt = 0; mt < 4; mt++)
#pragma unroll
            for (int nt = 0; nt < 4; nt++)
#pragma unroll
                for (int i = 0; i < 4; i++) acc[mt][nt][i] = 0.0f;

#pragma unroll
        for (int ks = 0; ks < 2; ks++) {
            const uint32_t colOff = (uint32_t)(ks * 16 + lhalf) * 2;
            uint32_t bhi[4][2];
#pragma unroll
            for (int g = 0; g < 2; g++) {
                uint32_t r0, r1, r2, r3;
                uint32_t addr = uKH + ((uint32_t)(n0 + g * 16 + lrow) * QSTR) * 2 + colOff;
                LDSM_X4(r0, r1, r2, r3, addr);
                bhi[2 * g][0] = r0; bhi[2 * g][1] = r2;
                bhi[2 * g + 1][0] = r1; bhi[2 * g + 1][1] = r3;
            }
            uint32_t a[4][4];
#pragma unroll
            for (int mt = 0; mt < 4; mt++) {
                uint32_t addr = uQH + ((uint32_t)(m0 + mt * 16 + lrow) * QSTR) * 2 + colOff;
                LDSM_X4(a[mt][0], a[mt][1], a[mt][2], a[mt][3], addr);
            }
#pragma unroll
            for (int mt = 0; mt < 4; mt++)
#pragma unroll
                for (int nt = 0; nt < 4; nt++)
                    mma_bf16(acc[mt][nt], a[mt][0], a[mt][1], a[mt][2], a[mt][3],
                             bhi[nt][0], bhi[nt][1]);
            uint32_t blo[4][2];
#pragma unroll
            for (int g = 0; g < 2; g++) {
                uint32_t r0, r1, r2, r3;
                uint32_t addr = uKL + ((uint32_t)(n0 + g * 16 + lrow) * QSTR) * 2 + colOff;
                LDSM_X4(r0, r1, r2, r3, addr);
                blo[2 * g][0] = r0; blo[2 * g][1] = r2;
                blo[2 * g + 1][0] = r1; blo[2 * g + 1][1] = r3;
            }
#pragma unroll
            for (int mt = 0; mt < 4; mt++)
#pragma unroll
                for (int nt = 0; nt < 4; nt++)
                    mma_bf16(acc[mt][nt], a[mt][0], a[mt][1], a[mt][2], a[mt][3],
                             blo[nt][0], blo[nt][1]);
#pragma unroll
            for (int mt = 0; mt < 4; mt++) {
                uint32_t addr = uQL + ((uint32_t)(m0 + mt * 16 + lrow) * QSTR) * 2 + colOff;
                LDSM_X4(a[mt][0], a[mt][1], a[mt][2], a[mt][3], addr);
            }
#pragma unroll
            for (int mt = 0; mt < 4; mt++)
#pragma unroll
                for (int nt = 0; nt < 4; nt++)
                    mma_bf16(acc[mt][nt], a[mt][0], a[mt][1], a[mt][2], a[mt][3],
                             bhi[nt][0], bhi[nt][1]);
        }

        // ALL warps must finish reading Q/K before P_lo overwrites that region
        __syncthreads();

#pragma unroll
        for (int mt = 0; mt < 4; mt++) {
            const int row0 = m0 + mt * 16 + cr;
            float s0 = 0.0f, s1 = 0.0f;
#pragma unroll
            for (int nt = 0; nt < 4; nt++) {
                const int col = n0 + nt * 8 + cc2;
                float2 mv0 = *(const float2*)(mask + mbase + (long)row0 * 128 + col);
                float2 mv1 = *(const float2*)(mask + mbase + (long)(row0 + 8) * 128 + col);
                float p00 = __expf(acc[mt][nt][0] * mv0.x);
                float p01 = __expf(acc[mt][nt][1] * mv0.y);
                float p10 = __expf(acc[mt][nt][2] * mv1.x);
                float p11 = __expf(acc[mt][nt][3] * mv1.y);
                s0 += p00 + p01;
                s1 += p10 + p11;
                __nv_bfloat16 h00 = __float2bfloat16_rn(p00);
                __nv_bfloat16 h01 = __float2bfloat16_rn(p01);
                __nv_bfloat16 h10 = __float2bfloat16_rn(p10);
                __nv_bfloat16 h11 = __float2bfloat16_rn(p11);
                *(uint32_t*)(smem + APH + row0 * PSTR + col) =
                    packbf(__bfloat162float(h00), __bfloat162float(h01));
                *(uint32_t*)(smem + APH + (row0 + 8) * PSTR + col) =
                    packbf(__bfloat162float(h10), __bfloat162float(h11));
                *(uint32_t*)(smem + APL + row0 * PSTR + col) =
                    packbf(p00 - __bfloat162float(h00), p01 - __bfloat162float(h01));
                *(uint32_t*)(smem + APL + (row0 + 8) * PSTR + col) =
                    packbf(p10 - __bfloat162float(h10), p11 - __bfloat162float(h11));
            }
            s0 += __shfl_xor_sync(0xffffffffu, s0, 1);
            s0 += __shfl_xor_sync(0xffffffffu, s0, 2);
            s1 += __shfl_xor_sync(0xffffffffu, s1, 1);
            s1 += __shfl_xor_sync(0xffffffffu, s1, 2);
            if ((lane & 3) == 0) {
                atomicAdd(&rowsum[row0], s0);
                atomicAdd(&rowsum[row0 + 8], s1);
            }
        }
    }
    __syncthreads();

    // ======== PV phase: 3 passes (Phi*Vhi + Phi*Vlo + Plo*Vhi) ========
    {
        const int m0 = warp * 16;
        const uint32_t uPH = smem_u32(smem + APH), uPL = smem_u32(smem + APL);
        const uint32_t uVH = smem_u32(smem + AVTH), uVL = smem_u32(smem + AVTL);

        float acc[4][4];
#pragma unroll
        for (int nt = 0; nt < 4; nt++)
#pragma unroll
            for (int i = 0; i < 4; i++) acc[nt][i] = 0.0f;

#pragma unroll
        for (int ks = 0; ks < 8; ks++) {
            const uint32_t colOff = (uint32_t)(ks * 16 + lhalf) * 2;
            uint32_t bhi[4][2];
#pragma unroll
            for (int g = 0; g < 2; g++) {
                uint32_t r0, r1, r2, r3;
                uint32_t addr = uVH + ((uint32_t)(g * 16 + lrow) * PSTR) * 2 + colOff;
                LDSM_X4(r0, r1, r2, r3, addr);
                bhi[2 * g][0] = r0; bhi[2 * g][1] = r2;
                bhi[2 * g + 1][0] = r1; bhi[2 * g + 1][1] = r3;
            }
            uint32_t a[4];
            {
                uint32_t addr = uPH + ((uint32_t)(m0 + lrow) * PSTR) * 2 + colOff;
                LDSM_X4(a[0], a[1], a[2], a[3], addr);
            }
#pragma unroll
            for (int nt = 0; nt < 4; nt++)
                mma_bf16(acc[nt], a[0], a[1], a[2], a[3], bhi[nt][0], bhi[nt][1]);
            uint32_t blo[4][2];
#pragma unroll
            for (int g = 0; g < 2; g++) {
                uint32_t r0, r1, r2, r3;
                uint32_t addr = uVL + ((uint32_t)(g * 16 + lrow) * PSTR) * 2 + colOff;
                LDSM_X4(r0, r1, r2, r3, addr);
                blo[2 * g][0] = r0; blo[2 * g][1] = r2;
                blo[2 * g + 1][0] = r1; blo[2 * g + 1][1] = r3;
            }
#pragma unroll
            for (int nt = 0; nt < 4; nt++)
                mma_bf16(acc[nt], a[0], a[1], a[2], a[3], blo[nt][0], blo[nt][1]);
            {
                uint32_t addr = uPL + ((uint32_t)(m0 + lrow) * PSTR) * 2 + colOff;
                LDSM_X4(a[0], a[1], a[2], a[3], addr);
            }
#pragma unroll
            for (int nt = 0; nt < 4; nt++)
                mma_bf16(acc[nt], a[0], a[1], a[2], a[3], bhi[nt][0], bhi[nt][1]);
        }

        const int row0 = m0 + cr;
        const float inv0 = 1.0f / rowsum[row0];
        const float inv1 = 1.0f / rowsum[row0 + 8];
#pragma unroll
        for (int nt = 0; nt < 4; nt++) {
            const int col = nt * 8 + cc2;
            *(float2*)(out + base + (long)row0 * 128 + col) =
                make_float2(acc[nt][0] * inv0, acc[nt][1] * inv0);
            *(float2*)(out + base + (long)(row0 + 8) * 128 + col) =
                make_float2(acc[nt][2] * inv1, acc[nt][3] * inv1);
        }
    }
}

// ---------------- out = LayerNorm(A + affine(B)) per row (affine from raw stats) ----------------
__global__ void add_ln_kernel(const float* __restrict__ A,
                              const float* __restrict__ B,
                              const float* __restrict__ sumB, const float* __restrict__ sqB,
                              const float* __restrict__ gB, const float* __restrict__ bB,
                              const float* __restrict__ gam,
                              const float* __restrict__ bet,
                              float* __restrict__ Out) {
    __shared__ float sc[128], sh[128];
    const int tid = threadIdx.x;
    if (tid < 128) {
        if (gB) bn_affine(sumB, sqB, gB, bB, tid, sc[tid], sh[tid]);
        else { sc[tid] = 1.0f; sh[tid] = 0.0f; }
    }
    __syncthreads();

    const int w = tid >> 5, lane = tid & 31;
    const long row = (long)blockIdx.x * 8 + w;
    const float* a = A + row * 128;
    const float* b = B + row * 128;

    float x[4];
    float s = 0.0f, s2 = 0.0f;
#pragma unroll
    for (int i = 0; i < 4; i++) {
        int c = lane + 32 * i;
        x[i] = a[c] + b[c] * sc[c] + sh[c];
        s += x[i];
        s2 += x[i] * x[i];
    }
#pragma unroll
    for (int o = 16; o > 0; o >>= 1) {
        s  += __shfl_xor_sync(0xffffffffu, s, o);
        s2 += __shfl_xor_sync(0xffffffffu, s2, o);
    }
    const float m = s * (1.0f / 128.0f);
    const float var = s2 * (1.0f / 128.0f) - m * m;
    const float r = rsqrtf(var + EPS);
#pragma unroll
    for (int i = 0; i < 4; i++) {
        int c = lane + 32 * i;
        Out[row * 128 + c] = (x[i] - m) * r * gam[c] + bet[c];
    }
}

// ---------------- h = LN(O + affine_ff(F)) + affine_sk(S); optional fused gather ----------------
__global__ void ln_add_affine_kernel(const float* __restrict__ O,
                                     const float* __restrict__ F,
                                     const float* __restrict__ sumF, const float* __restrict__ sqF,
                                     const float* __restrict__ gF, const float* __restrict__ bF,
                                     const float* __restrict__ Sk,
                                     const float* __restrict__ sumS, const float* __restrict__ sqS,
                                     const float* __restrict__ gS, const float* __restrict__ bS,
                                     const float* __restrict__ gam,
                                     const float* __restrict__ bet,
                                     float* __restrict__ Out,
                                     float* __restrict__ gatherOut) {
    __shared__ float sc4[128], sh4[128], sc5[128], sh5[128];
    const int tid = threadIdx.x;
    if (tid < 128) {
        bn_affine(sumF, sqF, gF, bF, tid, sc4[tid], sh4[tid]);
    } else {
        int c = tid - 128;
        bn_affine(sumS, sqS, gS, bS, c, sc5[c], sh5[c]);
    }
    __syncthreads();

    const int w = tid >> 5, lane = tid & 31;
    const long row = (long)blockIdx.x * 8 + w;
    const float* o = O + row * 128;
    const float* f = F + row * 128;
    const float* sk = Sk + row * 128;

    float x[4];
    float s = 0.0f, s2 = 0.0f;
#pragma unroll
    for (int i = 0; i < 4; i++) {
        int c = lane + 32 * i;
        x[i] = o[c] + f[c] * sc4[c] + sh4[c];
        s += x[i];
        s2 += x[i] * x[i];
    }
#pragma unroll
    for (int off = 16; off > 0; off >>= 1) {
        s  += __shfl_xor_sync(0xffffffffu, s, off);
        s2 += __shfl_xor_sync(0xffffffffu, s2, off);
    }
    const float m = s * (1.0f / 128.0f);
    const float var = s2 * (1.0f / 128.0f) - m * m;
    const float r = rsqrtf(var + EPS);
    const bool doGather = (gatherOut != 0) && ((row & 127) == 0);
#pragma unroll
    for (int i = 0; i < 4; i++) {
        int c = lane + 32 * i;
        float val = (x[i] - m) * r * gam[c] + bet[c] + sk[c] * sc5[c] + sh5[c];
        Out[row * 128 + c] = val;
        if (doGather) gatherOut[(row >> 7) * 128 + c] = val;
    }
}

// ---------------- host orchestration ----------------
extern "C" void kernel_launch(void* const* d_in, const int* in_sizes, int n_in,
                              void* d_out, int out_size) {
    const float* x        = (const float*)d_in[0];
    const float* mask     = (const float*)d_in[1];
    const float* lin_in_W = (const float*)d_in[2];
    const float* lin_in_b = (const float*)d_in[3];
    const float* in_bn_g  = (const float*)d_in[4];
    const float* in_bn_b  = (const float*)d_in[5];
    const float* q_W      = (const float*)d_in[6];
    const float* q_b      = (const float*)d_in[7];
    const float* q_bn_g   = (const float*)d_in[8];
    const float* q_bn_b   = (const float*)d_in[9];
    const float* k_W      = (const float*)d_in[10];
    const float* k_b      = (const float*)d_in[11];
    const float* k_bn_g   = (const float*)d_in[12];
    const float* k_bn_b   = (const float*)d_in[13];
    const float* v_W      = (const float*)d_in[14];
    const float* v_b      = (const float*)d_in[15];
    const float* v_bn_g   = (const float*)d_in[16];
    const float* v_bn_b   = (const float*)d_in[17];
    const float* ln_g     = (const float*)d_in[18];
    const float* ln_b     = (const float*)d_in[19];
    const float* ff_W     = (const float*)d_in[20];
    const float* ff_b     = (const float*)d_in[21];
    const float* ff_bn_g  = (const float*)d_in[22];
    const float* ff_bn_b  = (const float*)d_in[23];
    const float* skip_W   = (const float*)d_in[24];
    const float* skip_b   = (const float*)d_in[25];
    const float* skip_bn_g= (const float*)d_in[26];
    const float* skip_bn_b= (const float*)d_in[27];
    float* out = (float*)d_out;

    cudaFuncSetAttribute(gemm_tc_kernel, cudaFuncAttributeMaxDynamicSharedMemorySize, GEMM_SMEM);
    cudaFuncSetAttribute(attn_kernel, cudaFuncAttributeMaxDynamicSharedMemorySize, ATTN_SMEM);

    float *bh, *bt, *bq, *bk, *bv, *bs, *ba, *bo, *bf, *bsum, *bsq;
    cudaGetSymbolAddress((void**)&bh, g_h);
    cudaGetSymbolAddress((void**)&bt, g_t);
    cudaGetSymbolAddress((void**)&bq, g_q);
    cudaGetSymbolAddress((void**)&bk, g_k);
    cudaGetSymbolAddress((void**)&bv, g_v);
    cudaGetSymbolAddress((void**)&bs, g_s);
    cudaGetSymbolAddress((void**)&ba, g_a);
    cudaGetSymbolAddress((void**)&bo, g_o);
    cudaGetSymbolAddress((void**)&bf, g_f);
    cudaGetSymbolAddress((void**)&bsum, g_stat_sum);
    cudaGetSymbolAddress((void**)&bsq, g_stat_sq);

    auto SUM = [&](int i) { return bsum + i * DD; };
    auto SQ  = [&](int i) { return bsq + i * DD; };

    const int GEMM_GRID = M_ROWS / 128;   // 1024

    // launch 1: zero all stat slots
    zero_stats_kernel<<<(NSLOT * DD + 255) / 256, 256>>>();

    // launch 2: t0 = x @ Win^T + b ; stats -> slot 0
    gemm_tc_kernel<<<GEMM_GRID, 512, GEMM_SMEM>>>(
        x, 0, 0, 0, 0,
        lin_in_W, lin_in_W, lin_in_W, lin_in_W,
        lin_in_b, lin_in_b, lin_in_b, lin_in_b,
        bt, bt, bt, bt,
        SUM(0), SUM(0), SUM(0), SUM(0), SQ(0), SQ(0), SQ(0), SQ(0), 1);

    // launch 3: spacer so the profiler's fixed slot (#4) captures the QKVS GEMM
    noop_kernel<<<1, 32>>>();

    for (int l = 0; l < LL; l++) {
        const long wOff = (long)l * DD * DD;
        const long vOff = (long)l * DD;
        const float* hp = (l == 0) ? bt : bh;
        const int sq_ = 1 + l * 5, sk_ = 2 + l * 5, sv_ = 3 + l * 5,
                  ss_ = 4 + l * 5, sf_ = 5 + l * 5;
        const float* hSum = (l == 0) ? SUM(0) : 0;
        const float* hSq  = (l == 0) ? SQ(0) : 0;
        const float* hG   = (l == 0) ? in_bn_g : 0;
        const float* hB   = (l == 0) ? in_bn_b : 0;

        // fused Q/K/V/skip GEMM (launch 4 for l=0 — ncu target)
        gemm_tc_kernel<<<GEMM_GRID, 512, GEMM_SMEM>>>(
            hp, hSum, hSq, hG, hB,
            q_W + wOff, k_W + wOff, v_W + wOff, skip_W + wOff,
            q_b + vOff, k_b + vOff, v_b + vOff, skip_b + vOff,
            bq, bk, bv, bs,
            SUM(sq_), SUM(sk_), SUM(sv_), SUM(ss_),
            SQ(sq_), SQ(sk_), SQ(sv_), SQ(ss_), 4);

        // attention
        dim3 agrid(HH, NB);
        attn_kernel<<<agrid, 256, ATTN_SMEM>>>(
            bq, bk, bv, mask,
            SUM(sq_), SQ(sq_), q_bn_g + vOff, q_bn_b + vOff,
            SUM(sk_), SQ(sk_), k_bn_g + vOff, k_bn_b + vOff,
            SUM(sv_), SQ(sv_), v_bn_g + vOff, v_bn_b + vOff,
            ba);

        // out = LN(agg + h)
        add_ln_kernel<<<M_ROWS / 8, 256>>>(ba, hp, hSum, hSq, hG, hB,
                                           ln_g + vOff, ln_b + vOff, bo);

        // ff GEMM -> slot sf_
        gemm_tc_kernel<<<GEMM_GRID, 512, GEMM_SMEM>>>(
            bo, 0, 0, 0, 0,
            ff_W + wOff, ff_W + wOff, ff_W + wOff, ff_W + wOff,
            ff_b + vOff, ff_b + vOff, ff_b + vOff, ff_b + vOff,
            bf, bf, bf, bf,
            SUM(sf_), SUM(sf_), SUM(sf_), SUM(sf_),
            SQ(sf_), SQ(sf_), SQ(sf_), SQ(sf_), 1);

        // h = LN(out + affine_ff(ff)) + affine_skip(skip)  [+ fused gather on last layer]
        ln_add_affine_kernel<<<M_ROWS / 8, 256>>>(
            bo, bf, SUM(sf_), SQ(sf_), ff_bn_g + vOff, ff_bn_b + vOff,
            bs, SUM(ss_), SQ(ss_), skip_bn_g + vOff, skip_bn_b + vOff,
            ln_g + vOff, ln_b + vOff, bh,
            (l == LL - 1) ? out : 0);
    }
}